// round 13
// baseline (speedup 1.0000x reference)
#include <cuda_runtime.h>
#include <cstdint>

// RiemannSolver R12: single fused kernel. Coalesced load of 256 consecutive
// cells per CTA -> classify -> CTA-local compaction into route groups in
// shared memory (padded to 32-cell warp-tiles, <=10 tiles/CTA) -> per-warp
// m16n8k8 tf32 MMA layer-1 (B fragments read directly from W1/b1 via L1) ->
// MUFU tanh + layer-2 epilogue -> scattered 12B/cell output write.
// No global counters, no bucket arrays, no second kernel, no gather.

#define GAMMA_F 1.6666666666666667f
#define SA_STRIDE 28          // floats/row: 16B-aligned STS.128, conflict-free A frags
#define MAX_SLOTS 320         // 10 tiles * 32 (hard bound, see analysis)

__device__ __forceinline__ uint32_t f2tf32(float x) {
    uint32_t r;
    asm("cvt.rna.tf32.f32 %0, %1;" : "=r"(r) : "f"(x));
    return r;
}

// m16n8k8 tf32 (fragment mapping verified R8/R12):
//  A: a0=(g,tig) a1=(g+8,tig) a2=(g,tig+4) a3=(g+8,tig+4)
//  B: b0=(tig,n) b1=(tig+4,n)
//  D: d0=(g,2tig) d1=(g,2tig+1) d2=(g+8,2tig) d3=(g+8,2tig+1)
__device__ __forceinline__ void mma_tf32_k8(float* d, uint32_t a0, uint32_t a1,
                                            uint32_t a2, uint32_t a3,
                                            uint32_t b0, uint32_t b1) {
    asm volatile(
        "mma.sync.aligned.m16n8k8.row.col.f32.tf32.tf32.f32 "
        "{%0,%1,%2,%3}, {%4,%5,%6,%7}, {%8,%9}, {%0,%1,%2,%3};"
        : "+f"(d[0]), "+f"(d[1]), "+f"(d[2]), "+f"(d[3])
        : "r"(a0), "r"(a1), "r"(a2), "r"(a3), "r"(b0), "r"(b1));
}

__device__ __forceinline__ float tanh_mufu(float x) {
    float r;
    asm("tanh.approx.f32 %0, %1;" : "=f"(r) : "f"(x));
    return r;
}

__global__ __launch_bounds__(256)
void k_fused(
    const float* __restrict__ P, const float* __restrict__ U,
    const float* __restrict__ F,
    const float* __restrict__ cmax, const float* __restrict__ cmin,
    const float* __restrict__ W1_0, const float* __restrict__ b1_0,
    const float* __restrict__ W2_0, const float* __restrict__ b2_0,
    const float* __restrict__ W1_1, const float* __restrict__ b1_1,
    const float* __restrict__ W2_1, const float* __restrict__ b2_1,
    const float* __restrict__ W1_2, const float* __restrict__ b1_2,
    const float* __restrict__ W2_2, const float* __restrict__ b2_2,
    float* __restrict__ out, int N)
{
    __shared__ __align__(16) float sA[MAX_SLOTS * SA_STRIDE];  // 35.8 KB
    __shared__ __align__(16) float sw2[3 * 256];               // 3 KB (W2 padded 64x4)
    __shared__ int sMeta[MAX_SLOTS];
    __shared__ int shCnt[3];
    __shared__ int wBase[8][3];

    int tid = threadIdx.x;
    int wid = tid >> 5;
    int lane = tid & 31;
    int g = lane >> 2;
    int tig = lane & 3;

    if (tid < 3) shCnt[tid] = 0;
    sMeta[tid] = 0;
    if (tid < MAX_SLOTS - 256) sMeta[256 + tid] = 0;
    __syncthreads();

    // ---- phase 1: coalesced load + classify + inline HLLE/vacuum
    int n = blockIdx.x * 256 + tid;
    bool have = n < N;
    int route = 6;
    bool flip = false;
    float2 P0, P1, P2, U0, U1, U2, F0, F1, F2;
    float cx = 0.0f, cnn = 0.0f;

    if (have) {
        const float2* Pp = reinterpret_cast<const float2*>(P) + (size_t)n * 3;
        const float2* Up = reinterpret_cast<const float2*>(U) + (size_t)n * 3;
        const float2* Fp = reinterpret_cast<const float2*>(F) + (size_t)n * 3;
        P0 = Pp[0]; P1 = Pp[1]; P2 = Pp[2];
        U0 = Up[0]; U1 = Up[1]; U2 = Up[2];
        F0 = Fp[0]; F1 = Fp[1]; F2 = Fp[2];
        cx = cmax[n];
        cnn = cmin[n];

        flip = P1.y > P1.x;
        if (flip) {
            float t;
            t = P0.x; P0.x = P0.y; P0.y = t;
            t = P1.x; P1.x = P1.y; P1.y = t;
            t = P2.x; P2.x = -P2.y; P2.y = -t;
            t = U0.x; U0.x = U0.y; U0.y = t;
            t = U1.x; U1.x = U1.y; U1.y = t;
            t = U2.x; U2.x = -U2.y; U2.y = -t;
            t = F0.x; F0.x = -F0.y; F0.y = -t;
            t = F1.x; F1.x = -F1.y; F1.y = -t;
            t = F2.x; F2.x = F2.y;  F2.y = t;
        }
        float d0 = fabsf(P0.y - P0.x);
        float d1 = fabsf(P1.y - P1.x);
        float d2 = fabsf(P2.y - P2.x);
        bool cont = fmaxf(d0, fmaxf(d1, d2)) < 0.005f;

        float q0 = P1.x, q1 = P1.y;
        float c0 = sqrtf(GAMMA_F * q0 / P0.x);
        float c1 = sqrtf(GAMMA_F * q1 / P0.y);
        float dv = P2.y - P2.x;
        float num = c0 + c1 - 0.33333334f * dv;
        float pz0 = exp2f(0.2f * __log2f(q0));
        float pz1 = exp2f(0.2f * __log2f(q1));
        float den = c0 / pz0 + c1 / pz1;
        float ps = fmaxf(num / den, 1e-8f);
        float ps2 = ps * ps;
        float pstar = ps2 * ps2 * ps;
        bool vac = dv >= 3.0f * (c0 + c1);
        bool dsb = pstar > fmaxf(q0, q1);
        bool drb = pstar < fminf(q0, q1);
        int label = vac ? 3 : (drb ? 1 : (dsb ? 0 : 2));
        route = cont ? 4 : label;

        if (route >= 3) {
            float* op = out + (size_t)n * 3;
            if (route == 3) {
                op[0] = 0.0f; op[1] = 0.0f; op[2] = 0.0f;
            } else {
                float inv = 1.0f / (cx - cnn);
                float cc = cx * cnn;
                float o0 = (cx * F0.x - cnn * F0.y + cc * (U0.y - U0.x)) * inv;
                float o1 = (cx * F1.x - cnn * F1.y + cc * (U1.y - U1.x)) * inv;
                float o2 = (cx * F2.x - cnn * F2.y + cc * (U2.y - U2.x)) * inv;
                if (flip) { o0 = -o0; o1 = -o1; }
                op[0] = o0; op[1] = o1; op[2] = o2;
            }
        }
    }

    // ---- phase 2: CTA-local compaction (ballot + smem atomics)
    int myrank = 0;
#pragma unroll
    for (int r = 0; r < 3; r++) {
        unsigned bal = __ballot_sync(0xffffffffu, route == r);
        if (route == r) myrank = __popc(bal & ((1u << lane) - 1u));
        if (lane == 0 && bal) wBase[wid][r] = atomicAdd(&shCnt[r], __popc(bal));
    }
    __syncthreads();

    int cc0 = shCnt[0], cc1 = shCnt[1], cc2 = shCnt[2];
    int tiles0 = (cc0 + 31) >> 5;
    int tiles1 = (cc1 + 31) >> 5;
    int tiles2 = (cc2 + 31) >> 5;
    int T = tiles0 + tiles1 + tiles2;
    int tb1 = tiles0, tb2 = tiles0 + tiles1;

    // ---- phase 3: stage features (tf32 + bias col) at compacted slot
    if (have && route < 3) {
        int base = (route == 0) ? 0 : (route == 1) ? tiles0 * 32 : (tiles0 + tiles1) * 32;
        int slot = base + wBase[wid][route] + myrank;
        float4* r4 = reinterpret_cast<float4*>(&sA[slot * SA_STRIDE]);
        r4[0] = make_float4(__uint_as_float(f2tf32(P0.x)), __uint_as_float(f2tf32(P0.y)),
                            __uint_as_float(f2tf32(P1.x)), __uint_as_float(f2tf32(P1.y)));
        r4[1] = make_float4(__uint_as_float(f2tf32(P2.x)), __uint_as_float(f2tf32(P2.y)),
                            __uint_as_float(f2tf32(U0.x)), __uint_as_float(f2tf32(U0.y)));
        r4[2] = make_float4(__uint_as_float(f2tf32(U1.x)), __uint_as_float(f2tf32(U1.y)),
                            __uint_as_float(f2tf32(U2.x)), __uint_as_float(f2tf32(U2.y)));
        r4[3] = make_float4(__uint_as_float(f2tf32(F0.x)), __uint_as_float(f2tf32(F0.y)),
                            __uint_as_float(f2tf32(F1.x)), __uint_as_float(f2tf32(F1.y)));
        r4[4] = make_float4(__uint_as_float(f2tf32(F2.x)), __uint_as_float(f2tf32(F2.y)),
                            __uint_as_float(f2tf32(cx)),   __uint_as_float(f2tf32(cnn)));
        r4[5] = make_float4(1.0f, 0.0f, 0.0f, 0.0f);   // bias column k=20, pad 21..23
        sMeta[slot] = n | (1 << 29) | (flip ? (1 << 30) : 0);
    }

    // stage W2 (padded 64x4) for all 3 routes
    for (int idx = tid; idx < 768; idx += 256) {
        int r = idx >> 8;
        int jj = (idx & 255) >> 2;
        int kk = idx & 3;
        const float* W2r = (r == 0) ? W2_0 : (r == 1) ? W2_1 : W2_2;
        sw2[idx] = (kk < 3) ? W2r[jj * 3 + kk] : 0.0f;
    }
    __syncthreads();

    // ---- phase 4: warp-tile loop
    for (int t = wid; t < T; t += 8) {
        int rt = (t >= tb1) + (t >= tb2);
        const float* W1r = (rt == 0) ? W1_0 : (rt == 1) ? W1_1 : W1_2;
        const float* b1r = (rt == 0) ? b1_0 : (rt == 1) ? b1_1 : b1_2;
        const float* b2r = (rt == 0) ? b2_0 : (rt == 1) ? b2_1 : b2_2;
        const float* sAw = sA + t * 32 * SA_STRIDE;
        const float* w2r = sw2 + rt * 256;

        float os[2][2][3];
#pragma unroll
        for (int m = 0; m < 2; m++)
#pragma unroll
            for (int r = 0; r < 2; r++)
#pragma unroll
                for (int c = 0; c < 3; c++) os[m][r][c] = 0.0f;

#pragma unroll
        for (int h = 0; h < 2; h++) {
            float d[2][4][4];
#pragma unroll
            for (int m = 0; m < 2; m++)
#pragma unroll
                for (int nt = 0; nt < 4; nt++)
#pragma unroll
                    for (int v = 0; v < 4; v++) d[m][nt][v] = 0.0f;

#pragma unroll
            for (int kt = 0; kt < 3; kt++) {
                int ak = g * SA_STRIDE + kt * 8 + tig;
                uint32_t a[2][4];
#pragma unroll
                for (int m = 0; m < 2; m++) {
                    int base = ak + m * 16 * SA_STRIDE;
                    a[m][0] = __float_as_uint(sAw[base]);
                    a[m][1] = __float_as_uint(sAw[base + 8 * SA_STRIDE]);
                    a[m][2] = __float_as_uint(sAw[base + 4]);
                    a[m][3] = __float_as_uint(sAw[base + 8 * SA_STRIDE + 4]);
                }
                int k0 = kt * 8 + tig;            // 0..19 always valid W1 row
#pragma unroll
                for (int nt = 0; nt < 4; nt++) {
                    int nn = h * 32 + nt * 8 + g; // hidden unit index
                    float w0f = W1r[k0 * 64 + nn];
                    float w1f;
                    if (kt < 2) w1f = W1r[(k0 + 4) * 64 + nn];
                    else        w1f = (tig == 0) ? b1r[nn] : 0.0f;  // row 20 = bias
                    uint32_t b0 = f2tf32(w0f);
                    uint32_t b1v = f2tf32(w1f);
#pragma unroll
                    for (int m = 0; m < 2; m++)
                        mma_tf32_k8(d[m][nt], a[m][0], a[m][1], a[m][2], a[m][3], b0, b1v);
                }
            }

            // epilogue for this half: MUFU tanh + layer-2 partials
#pragma unroll
            for (int nt = 0; nt < 4; nt++) {
                int j0 = (h * 4 + nt) * 8 + 2 * tig;
                float4 w2a = *reinterpret_cast<const float4*>(w2r + j0 * 4);
                float4 w2b = *reinterpret_cast<const float4*>(w2r + j0 * 4 + 4);
#pragma unroll
                for (int m = 0; m < 2; m++) {
                    float ta = tanh_mufu(d[m][nt][0]);
                    float tb = tanh_mufu(d[m][nt][1]);
                    float tc = tanh_mufu(d[m][nt][2]);
                    float td = tanh_mufu(d[m][nt][3]);
                    os[m][0][0] = fmaf(ta, w2a.x, fmaf(tb, w2b.x, os[m][0][0]));
                    os[m][0][1] = fmaf(ta, w2a.y, fmaf(tb, w2b.y, os[m][0][1]));
                    os[m][0][2] = fmaf(ta, w2a.z, fmaf(tb, w2b.z, os[m][0][2]));
                    os[m][1][0] = fmaf(tc, w2a.x, fmaf(td, w2b.x, os[m][1][0]));
                    os[m][1][1] = fmaf(tc, w2a.y, fmaf(td, w2b.y, os[m][1][1]));
                    os[m][1][2] = fmaf(tc, w2a.z, fmaf(td, w2b.z, os[m][1][2]));
                }
            }
        }

        // quad reduce (lanes xor 1, xor 2 share the same output row g)
#pragma unroll
        for (int m = 0; m < 2; m++)
#pragma unroll
            for (int r = 0; r < 2; r++)
#pragma unroll
                for (int c = 0; c < 3; c++) {
                    float v = os[m][r][c];
                    v += __shfl_xor_sync(0xffffffffu, v, 1);
                    v += __shfl_xor_sync(0xffffffffu, v, 2);
                    os[m][r][c] = v;
                }

        // lane q = lane&3 writes warp-local cell (q>>1)*16 + (q&1)*8 + g
        int q = lane & 3;
        int mm = q >> 1, rr = q & 1;
        int cl = mm * 16 + rr * 8 + g;
        int slot = t * 32 + cl;
        int meta = sMeta[slot];
        if (meta & (1 << 29)) {
            float o0 = os[mm][rr][0] + b2r[0];
            float o1 = os[mm][rr][1] + b2r[1];
            float o2 = os[mm][rr][2] + b2r[2];
            if (meta & (1 << 30)) { o0 = -o0; o1 = -o1; }
            int cellid = meta & 0x1FFFFFFF;
            float* op = out + (size_t)cellid * 3;
            op[0] = o0; op[1] = o1; op[2] = o2;
        }
    }
}

// ---------------------------------------------------------------------------
extern "C" void kernel_launch(void* const* d_in, const int* in_sizes, int n_in,
                              void* d_out, int out_size) {
    const float* P    = (const float*)d_in[0];
    const float* U    = (const float*)d_in[1];
    const float* F    = (const float*)d_in[2];
    const float* cmax = (const float*)d_in[3];
    const float* cmin = (const float*)d_in[4];
    const float* W1_ds = (const float*)d_in[5];
    const float* b1_ds = (const float*)d_in[6];
    const float* W2_ds = (const float*)d_in[7];
    const float* b2_ds = (const float*)d_in[8];
    const float* W1_dr = (const float*)d_in[9];
    const float* b1_dr = (const float*)d_in[10];
    const float* W2_dr = (const float*)d_in[11];
    const float* b2_dr = (const float*)d_in[12];
    const float* W1_rs = (const float*)d_in[13];
    const float* b1_rs = (const float*)d_in[14];
    const float* W2_rs = (const float*)d_in[15];
    const float* b2_rs = (const float*)d_in[16];

    int N = in_sizes[3];
    float* out = (float*)d_out;

    int grid = (N + 255) / 256;
    k_fused<<<grid, 256>>>(
        P, U, F, cmax, cmin,
        W1_ds, b1_ds, W2_ds, b2_ds,
        W1_dr, b1_dr, W2_dr, b2_dr,
        W1_rs, b1_rs, W2_rs, b2_rs,
        out, N);
}

// round 14
// speedup vs baseline: 1.3637x; 1.3637x over previous
#include <cuda_runtime.h>
#include <cstdint>

// RiemannSolver R13: R12 with the register cap removed (the isolated harmful
// variable). Two-kernel structure, m16n8k8 tf32 MMA, split-N accumulators,
// NO forced launch_bounds minimum -> no spills.
//
//  k_classify: route cells {0:ds,1:dr,2:rs}; vacuum/HLLE resolved inline;
//              blocks 0..2 stage tf32 weight blocks to gmem.
//  k_mlp: 256-thread CTA = 256 same-route cells. Per warp: M=32 cells,
//         N=64 hidden, K=24 (x_tf32[20] | 1.0 bias | 0 0 0) via m16n8k8.
//         N processed in two halves of 4 n-tiles; epilogue (MUFU tanh +
//         layer-2 partials) per half so accumulators are reused.

typedef unsigned long long u64;

#define NC 1048576
#define GAMMA_F 1.6666666666666667f
#define TILE 256
#define KDIM 24
#define SA_STRIDE 28      // floats/row: conflict-free STS.128 + A-frag LDS
#define SB_STRIDE 72      // floats/row: 72%32==8 -> conflict-free B-frag LDS

__device__ int g_cnt[4];
__device__ int g_done;
__device__ int g_bucket[3 * NC];
__device__ float g_pB[3][KDIM * SB_STRIDE];
__device__ float g_pW2[3][256];
__device__ float g_pB2[3][4];

__device__ __forceinline__ uint32_t f2tf32(float x) {
    uint32_t r;
    asm("cvt.rna.tf32.f32 %0, %1;" : "=r"(r) : "f"(x));
    return r;
}

// m16n8k8 tf32: A: a0=(g,tig) a1=(g+8,tig) a2=(g,tig+4) a3=(g+8,tig+4)
//               B: b0=(tig,g) b1=(tig+4,g)
//               D: d0=(g,2tig) d1=(g,2tig+1) d2=(g+8,2tig) d3=(g+8,2tig+1)
__device__ __forceinline__ void mma_tf32_k8(float* d, uint32_t a0, uint32_t a1,
                                            uint32_t a2, uint32_t a3,
                                            uint32_t b0, uint32_t b1) {
    asm volatile(
        "mma.sync.aligned.m16n8k8.row.col.f32.tf32.tf32.f32 "
        "{%0,%1,%2,%3}, {%4,%5,%6,%7}, {%8,%9}, {%0,%1,%2,%3};"
        : "+f"(d[0]), "+f"(d[1]), "+f"(d[2]), "+f"(d[3])
        : "r"(a0), "r"(a1), "r"(a2), "r"(a3), "r"(b0), "r"(b1));
}

__device__ __forceinline__ float tanh_mufu(float x) {
    float r;
    asm("tanh.approx.f32 %0, %1;" : "=f"(r) : "f"(x));
    return r;
}

// ---------------------------------------------------------------------------
__global__ __launch_bounds__(256)
void k_classify(const float* __restrict__ P, const float* __restrict__ U,
                const float* __restrict__ F, const float* __restrict__ cmax,
                const float* __restrict__ cmin,
                const float* __restrict__ W1_0, const float* __restrict__ b1_0,
                const float* __restrict__ W2_0, const float* __restrict__ b2_0,
                const float* __restrict__ W1_1, const float* __restrict__ b1_1,
                const float* __restrict__ W2_1, const float* __restrict__ b2_1,
                const float* __restrict__ W1_2, const float* __restrict__ b1_2,
                const float* __restrict__ W2_2, const float* __restrict__ b2_2,
                float* __restrict__ out, int N) {
    __shared__ int shCnt[3];
    __shared__ int shBase[3];
    __shared__ int wBase[8][3];
    int tid = threadIdx.x;
    if (tid < 3) shCnt[tid] = 0;
    __syncthreads();

    int n = blockIdx.x * 256 + tid;
    int route = 5;
    bool flip = false;
    if (n < N) {
        const float2* Pp = reinterpret_cast<const float2*>(P) + (size_t)n * 3;
        float2 P0 = Pp[0], P1 = Pp[1], P2 = Pp[2];
        flip = P1.y > P1.x;
        if (flip) {
            float t;
            t = P0.x; P0.x = P0.y; P0.y = t;
            t = P1.x; P1.x = P1.y; P1.y = t;
            t = P2.x; P2.x = -P2.y; P2.y = -t;
        }
        float d0 = fabsf(P0.y - P0.x);
        float d1 = fabsf(P1.y - P1.x);
        float d2 = fabsf(P2.y - P2.x);
        bool cont = fmaxf(d0, fmaxf(d1, d2)) < 0.005f;

        float q0 = P1.x, q1 = P1.y;
        float c0 = sqrtf(GAMMA_F * q0 / P0.x);
        float c1 = sqrtf(GAMMA_F * q1 / P0.y);
        float dv = P2.y - P2.x;
        float num = c0 + c1 - 0.33333334f * dv;
        float pz0 = exp2f(0.2f * __log2f(q0));
        float pz1 = exp2f(0.2f * __log2f(q1));
        float den = c0 / pz0 + c1 / pz1;
        float ps = fmaxf(num / den, 1e-8f);
        float ps2 = ps * ps;
        float pstar = ps2 * ps2 * ps;
        bool vac = dv >= 3.0f * (c0 + c1);
        bool dsb = pstar > fmaxf(q0, q1);
        bool drb = pstar < fminf(q0, q1);
        int label = vac ? 3 : (drb ? 1 : (dsb ? 0 : 2));
        route = cont ? 4 : label;

        if (route >= 3) {
            float* op = out + (size_t)n * 3;
            if (route == 3) {
                op[0] = 0.0f; op[1] = 0.0f; op[2] = 0.0f;
            } else {
                const float2* Up = reinterpret_cast<const float2*>(U) + (size_t)n * 3;
                const float2* Fp = reinterpret_cast<const float2*>(F) + (size_t)n * 3;
                float2 U0 = Up[0], U1 = Up[1], U2 = Up[2];
                float2 F0 = Fp[0], F1 = Fp[1], F2 = Fp[2];
                if (flip) {
                    float t;
                    t = U0.x; U0.x = U0.y; U0.y = t;
                    t = U1.x; U1.x = U1.y; U1.y = t;
                    t = U2.x; U2.x = -U2.y; U2.y = -t;
                    t = F0.x; F0.x = -F0.y; F0.y = -t;
                    t = F1.x; F1.x = -F1.y; F1.y = -t;
                    t = F2.x; F2.x = F2.y;  F2.y = t;
                }
                float cx = cmax[n], cnn = cmin[n];
                float inv = 1.0f / (cx - cnn);
                float cc = cx * cnn;
                float o0 = (cx * F0.x - cnn * F0.y + cc * (U0.y - U0.x)) * inv;
                float o1 = (cx * F1.x - cnn * F1.y + cc * (U1.y - U1.x)) * inv;
                float o2 = (cx * F2.x - cnn * F2.y + cc * (U2.y - U2.x)) * inv;
                if (flip) { o0 = -o0; o1 = -o1; }
                op[0] = o0; op[1] = o1; op[2] = o2;
            }
        }
    }

    int lane = tid & 31, w = tid >> 5;
    int myrank = 0;
#pragma unroll
    for (int r = 0; r < 3; r++) {
        unsigned bal = __ballot_sync(0xffffffffu, route == r);
        if (route == r) myrank = __popc(bal & ((1u << lane) - 1u));
        if (lane == 0 && bal) wBase[w][r] = atomicAdd(&shCnt[r], __popc(bal));
    }
    __syncthreads();
    if (tid < 3) shBase[tid] = atomicAdd(&g_cnt[tid], shCnt[tid]);
    __syncthreads();
    if (route < 3) {
        int pos = shBase[route] + wBase[w][route] + myrank;
        g_bucket[route * NC + pos] = n;
    }

    // ---- blocks 0..2: stage tf32-converted weights for route r
    int r = blockIdx.x;
    if (r < 3) {
        const float* W1r = (r == 0) ? W1_0 : (r == 1) ? W1_1 : W1_2;
        const float* b1r = (r == 0) ? b1_0 : (r == 1) ? b1_1 : b1_2;
        const float* W2r = (r == 0) ? W2_0 : (r == 1) ? W2_1 : W2_2;
        const float* b2r = (r == 0) ? b2_0 : (r == 1) ? b2_1 : b2_2;
        for (int idx = tid; idx < KDIM * SB_STRIDE; idx += 256) {
            int k = idx / SB_STRIDE;
            int c = idx - k * SB_STRIDE;
            float v = 0.0f;
            if (c < 64) {
                if (k < 20)       v = __uint_as_float(f2tf32(W1r[k * 64 + c]));
                else if (k == 20) v = __uint_as_float(f2tf32(b1r[c]));
            }
            g_pB[r][idx] = v;
        }
        if (tid < 256) {
            int j = tid >> 2, kk = tid & 3;
            g_pW2[r][tid] = (kk < 3) ? W2r[j * 3 + kk] : 0.0f;
        }
        if (tid < 4) g_pB2[r][tid] = (tid < 3) ? b2r[tid] : 0.0f;
    }
}

// ---------------------------------------------------------------------------
__global__ __launch_bounds__(256)
void k_mlp(
    const float* __restrict__ P, const float* __restrict__ U,
    const float* __restrict__ F,
    const float* __restrict__ cmax, const float* __restrict__ cmin,
    float* __restrict__ out, int N)
{
    __shared__ __align__(16) float sA[8][32 * SA_STRIDE];
    __shared__ __align__(16) float sB[KDIM * SB_STRIDE];
    __shared__ __align__(16) float sw2[256];
    __shared__ float sb2[3];

    int tid = threadIdx.x;
    int wid = tid >> 5;
    int lane = tid & 31;
    int g = lane >> 2;
    int tig = lane & 3;

    int c0 = g_cnt[0], c1 = g_cnt[1], c2 = g_cnt[2];
    int t0 = (c0 + TILE - 1) / TILE;
    int t1 = (c1 + TILE - 1) / TILE;
    int t2 = (c2 + TILE - 1) / TILE;
    int b = blockIdx.x;
    int total = t0 + t1 + t2;

    if (b >= total) {
        __threadfence();
        if (tid == 0) {
            int old = atomicAdd(&g_done, 1);
            if (old == (int)gridDim.x - 1) {
                g_cnt[0] = 0; g_cnt[1] = 0; g_cnt[2] = 0;
                __threadfence();
                g_done = 0;
            }
        }
        return;
    }

    int route, tileIdx, cnt;
    if (b < t0)           { route = 0; tileIdx = b;           cnt = c0; }
    else if (b < t0 + t1) { route = 1; tileIdx = b - t0;      cnt = c1; }
    else                  { route = 2; tileIdx = b - t0 - t1; cnt = c2; }

    // ---- coalesced copy of pre-converted weights
    {
        const float4* src = reinterpret_cast<const float4*>(g_pB[route]);
        float4* dst = reinterpret_cast<float4*>(sB);
        const int nv = (KDIM * SB_STRIDE) / 4;     // 432
        for (int i = tid; i < nv; i += 256) dst[i] = src[i];
        const float4* s2 = reinterpret_cast<const float4*>(g_pW2[route]);
        float4* d2 = reinterpret_cast<float4*>(sw2);
        if (tid < 64) d2[tid] = s2[tid];
        if (tid < 3) sb2[tid] = g_pB2[route][tid];
    }

    // ---- gather + features
    int slot = tileIdx * TILE + tid;
    bool valid = slot < cnt;
    int cslot = valid ? slot : (cnt - 1);
    int cell = g_bucket[route * NC + cslot];

    const float2* Pp = reinterpret_cast<const float2*>(P) + (size_t)cell * 3;
    const float2* Up = reinterpret_cast<const float2*>(U) + (size_t)cell * 3;
    const float2* Fp = reinterpret_cast<const float2*>(F) + (size_t)cell * 3;
    float2 P0 = Pp[0], P1 = Pp[1], P2 = Pp[2];
    float2 U0 = Up[0], U1 = Up[1], U2 = Up[2];
    float2 F0 = Fp[0], F1 = Fp[1], F2 = Fp[2];
    float cx = cmax[cell];
    float cnn = cmin[cell];

    bool flip = P1.y > P1.x;
    if (flip) {
        float t;
        t = P0.x; P0.x = P0.y; P0.y = t;
        t = P1.x; P1.x = P1.y; P1.y = t;
        t = P2.x; P2.x = -P2.y; P2.y = -t;
        t = U0.x; U0.x = U0.y; U0.y = t;
        t = U1.x; U1.x = U1.y; U1.y = t;
        t = U2.x; U2.x = -U2.y; U2.y = -t;
        t = F0.x; F0.x = -F0.y; F0.y = -t;
        t = F1.x; F1.x = -F1.y; F1.y = -t;
        t = F2.x; F2.x = F2.y;  F2.y = t;
    }
    unsigned flipmask  = __ballot_sync(0xffffffffu, flip);
    unsigned validmask = __ballot_sync(0xffffffffu, valid);

    {
        float4* r4 = reinterpret_cast<float4*>(&sA[wid][lane * SA_STRIDE]);
        r4[0] = make_float4(__uint_as_float(f2tf32(P0.x)), __uint_as_float(f2tf32(P0.y)),
                            __uint_as_float(f2tf32(P1.x)), __uint_as_float(f2tf32(P1.y)));
        r4[1] = make_float4(__uint_as_float(f2tf32(P2.x)), __uint_as_float(f2tf32(P2.y)),
                            __uint_as_float(f2tf32(U0.x)), __uint_as_float(f2tf32(U0.y)));
        r4[2] = make_float4(__uint_as_float(f2tf32(U1.x)), __uint_as_float(f2tf32(U1.y)),
                            __uint_as_float(f2tf32(U2.x)), __uint_as_float(f2tf32(U2.y)));
        r4[3] = make_float4(__uint_as_float(f2tf32(F0.x)), __uint_as_float(f2tf32(F0.y)),
                            __uint_as_float(f2tf32(F1.x)), __uint_as_float(f2tf32(F1.y)));
        r4[4] = make_float4(__uint_as_float(f2tf32(F2.x)), __uint_as_float(f2tf32(F2.y)),
                            __uint_as_float(f2tf32(cx)),   __uint_as_float(f2tf32(cnn)));
        r4[5] = make_float4(1.0f, 0.0f, 0.0f, 0.0f);       // bias column k=20
    }
    __syncthreads();

    // ---- GEMM + fused epilogue, two N-halves (accumulators reused)
    const float* sAw = sA[wid];
    float os[2][2][3];
#pragma unroll
    for (int m = 0; m < 2; m++)
#pragma unroll
        for (int r = 0; r < 2; r++)
#pragma unroll
            for (int c = 0; c < 3; c++) os[m][r][c] = 0.0f;

#pragma unroll
    for (int h = 0; h < 2; h++) {
        float d[2][4][4];
#pragma unroll
        for (int m = 0; m < 2; m++)
#pragma unroll
            for (int nt = 0; nt < 4; nt++)
#pragma unroll
                for (int v = 0; v < 4; v++) d[m][nt][v] = 0.0f;

#pragma unroll
        for (int kt = 0; kt < 3; kt++) {
            int ak = g * SA_STRIDE + kt * 8 + tig;
            uint32_t a[2][4];
#pragma unroll
            for (int m = 0; m < 2; m++) {
                int base = ak + m * 16 * SA_STRIDE;
                a[m][0] = __float_as_uint(sAw[base]);
                a[m][1] = __float_as_uint(sAw[base + 8 * SA_STRIDE]);
                a[m][2] = __float_as_uint(sAw[base + 4]);
                a[m][3] = __float_as_uint(sAw[base + 8 * SA_STRIDE + 4]);
            }
            int bk = (kt * 8 + tig) * SB_STRIDE + h * 32 + g;
#pragma unroll
            for (int nt = 0; nt < 4; nt++) {
                uint32_t b0 = __float_as_uint(sB[bk + nt * 8]);
                uint32_t b1 = __float_as_uint(sB[bk + 4 * SB_STRIDE + nt * 8]);
#pragma unroll
                for (int m = 0; m < 2; m++)
                    mma_tf32_k8(d[m][nt], a[m][0], a[m][1], a[m][2], a[m][3], b0, b1);
            }
        }

        // epilogue for this half: MUFU tanh + layer-2 partials
#pragma unroll
        for (int nt = 0; nt < 4; nt++) {
            int j0 = (h * 4 + nt) * 8 + 2 * tig;
            float4 w2a = *reinterpret_cast<const float4*>(sw2 + j0 * 4);
            float4 w2b = *reinterpret_cast<const float4*>(sw2 + j0 * 4 + 4);
#pragma unroll
            for (int m = 0; m < 2; m++) {
                float ta = tanh_mufu(d[m][nt][0]);
                float tb = tanh_mufu(d[m][nt][1]);
                float tc = tanh_mufu(d[m][nt][2]);
                float td = tanh_mufu(d[m][nt][3]);
                os[m][0][0] = fmaf(ta, w2a.x, fmaf(tb, w2b.x, os[m][0][0]));
                os[m][0][1] = fmaf(ta, w2a.y, fmaf(tb, w2b.y, os[m][0][1]));
                os[m][0][2] = fmaf(ta, w2a.z, fmaf(tb, w2b.z, os[m][0][2]));
                os[m][1][0] = fmaf(tc, w2a.x, fmaf(td, w2b.x, os[m][1][0]));
                os[m][1][1] = fmaf(tc, w2a.y, fmaf(td, w2b.y, os[m][1][1]));
                os[m][1][2] = fmaf(tc, w2a.z, fmaf(td, w2b.z, os[m][1][2]));
            }
        }
    }

    // quad reduce (lanes xor 1, xor 2 share the same output row g)
#pragma unroll
    for (int m = 0; m < 2; m++)
#pragma unroll
        for (int r = 0; r < 2; r++)
#pragma unroll
            for (int c = 0; c < 3; c++) {
                float v = os[m][r][c];
                v += __shfl_xor_sync(0xffffffffu, v, 1);
                v += __shfl_xor_sync(0xffffffffu, v, 2);
                os[m][r][c] = v;
            }

    // lane q = lane&3 writes warp-local cell  (q>>1)*16 + (q&1)*8 + g
    int q = lane & 3;
    int mm = q >> 1, rr = q & 1;
    int cl = mm * 16 + rr * 8 + g;
    float o0 = os[mm][rr][0] + sb2[0];
    float o1 = os[mm][rr][1] + sb2[1];
    float o2 = os[mm][rr][2] + sb2[2];
    if ((flipmask >> cl) & 1) { o0 = -o0; o1 = -o1; }
    int cellid = __shfl_sync(0xffffffffu, cell, cl);
    if ((validmask >> cl) & 1) {
        float* op = out + (size_t)cellid * 3;
        op[0] = o0; op[1] = o1; op[2] = o2;
    }

    // ---- counter self-reset (last CTA)
    __syncthreads();
    __threadfence();
    if (tid == 0) {
        int old = atomicAdd(&g_done, 1);
        if (old == (int)gridDim.x - 1) {
            g_cnt[0] = 0; g_cnt[1] = 0; g_cnt[2] = 0;
            __threadfence();
            g_done = 0;
        }
    }
}

// ---------------------------------------------------------------------------
extern "C" void kernel_launch(void* const* d_in, const int* in_sizes, int n_in,
                              void* d_out, int out_size) {
    const float* P    = (const float*)d_in[0];
    const float* U    = (const float*)d_in[1];
    const float* F    = (const float*)d_in[2];
    const float* cmax = (const float*)d_in[3];
    const float* cmin = (const float*)d_in[4];
    const float* W1_ds = (const float*)d_in[5];
    const float* b1_ds = (const float*)d_in[6];
    const float* W2_ds = (const float*)d_in[7];
    const float* b2_ds = (const float*)d_in[8];
    const float* W1_dr = (const float*)d_in[9];
    const float* b1_dr = (const float*)d_in[10];
    const float* W2_dr = (const float*)d_in[11];
    const float* b2_dr = (const float*)d_in[12];
    const float* W1_rs = (const float*)d_in[13];
    const float* b1_rs = (const float*)d_in[14];
    const float* W2_rs = (const float*)d_in[15];
    const float* b2_rs = (const float*)d_in[16];

    int N = in_sizes[3];
    float* out = (float*)d_out;

    k_classify<<<(N + 255) / 256, 256>>>(
        P, U, F, cmax, cmin,
        W1_ds, b1_ds, W2_ds, b2_ds,
        W1_dr, b1_dr, W2_dr, b2_dr,
        W1_rs, b1_rs, W2_rs, b2_rs,
        out, N);
    int grid2 = (N + TILE - 1) / TILE + 3;
    k_mlp<<<grid2, 256>>>(P, U, F, cmax, cmin, out, N);
}